// round 2
// baseline (speedup 1.0000x reference)
#include <cuda_runtime.h>
#include <math.h>

// Problem dims (fixed for this problem instance)
#define Bc 4
#define Lc 2048
#define Hc 8
#define Dc 64
#define Mc 256
#define CHUNK 64
#define NCH (Lc/CHUNK)       // 32
#define BH (Bc*Hc)           // 32
#define NROWS (Bc*Lc*Hc)     // 65536

#define NORMC 0.35355339059327373f   // 64^(-1/4)
#define RATIO 0.0625f                // 1/sqrt(256)
#define DIAGC 0.0625f                // 0.5 * 64^(-1/2)
#define KEPS  1e-4f

// ----- scratch (static device arrays; no allocation) -----
__device__ float g_qp   [(size_t)BH*Lc*Mc];   // 64 MB  [bh][l][m] query features
__device__ float g_kdash[(size_t)BH*Lc*Mc];   // 64 MB  raw key dash
__device__ float g_kp   [(size_t)BH*Lc*Mc];   // 64 MB  key features
__device__ float g_kdiag[BH*Lc];
__device__ float g_kmax [BH];
__device__ float g_S    [(size_t)BH*NCH*Mc*Dc]; // 64 MB  chunk states -> exclusive prefix
__device__ float g_z    [(size_t)BH*NCH*Mc];

__device__ __forceinline__ void atomicMaxF(float* addr, float v){
    int old = __float_as_int(*addr);
    while (__int_as_float(old) < v){
        int assumed = old;
        old = atomicCAS((int*)addr, assumed, __float_as_int(v));
        if (old == assumed) break;
    }
}

__global__ void init_kernel(){
    if (threadIdx.x < BH) g_kmax[threadIdx.x] = -3.0e38f;
}

// ============================================================
// K1: features. X:[B,L,H,D] -> dash = norm * X @ P^T  (rows = b*L*H+l*H+h)
// queries: full feature (row-max stab), keys: store raw dash + diag + bh-max
// ============================================================
#define PT_S 260
#define XT_S 68

__global__ __launch_bounds__(256) void feat_kernel(const float* __restrict__ X,
                                                   const float* __restrict__ P,
                                                   int isQuery)
{
    extern __shared__ float sm[];
    float* Pt   = sm;                 // [64][PT_S] transposed projection
    float* xT   = Pt + 64*PT_S;       // [64][XT_S] transposed x rows
    float* ss_s = xT + 64*XT_S;       // [64] sum of squares per row
    const int tid = threadIdx.x;

    for (int i = tid; i < Mc*Dc; i += 256){
        int m = i >> 6, d = i & 63;
        Pt[d*PT_S + m] = P[i];
    }
    const int row0 = blockIdx.x * 64;
    const float* Xb = X + (size_t)row0 * Dc;
    for (int i = tid; i < 64*Dc; i += 256){
        int r = i >> 6, d = i & 63;
        xT[d*XT_S + r] = Xb[i];
    }
    __syncthreads();

    if (tid < 64){
        float s = 0.f;
        #pragma unroll
        for (int d = 0; d < 64; d++){ float xv = xT[d*XT_S + tid]; s += xv*xv; }
        ss_s[tid] = s;
    }

    const int ri = tid >> 5, mi = tid & 31;   // warp = ri, rows ri*8.., cols mi*8..
    float acc[8][8];
    #pragma unroll
    for (int i = 0; i < 8; i++)
        #pragma unroll
        for (int j = 0; j < 8; j++) acc[i][j] = 0.f;

    #pragma unroll 4
    for (int d = 0; d < 64; d++){
        float4 x0 = *(const float4*)&xT[d*XT_S + ri*8];
        float4 x1 = *(const float4*)&xT[d*XT_S + ri*8 + 4];
        float4 p0 = *(const float4*)&Pt[d*PT_S + mi*8];
        float4 p1 = *(const float4*)&Pt[d*PT_S + mi*8 + 4];
        float xv[8] = {x0.x,x0.y,x0.z,x0.w,x1.x,x1.y,x1.z,x1.w};
        float pv[8] = {p0.x,p0.y,p0.z,p0.w,p1.x,p1.y,p1.z,p1.w};
        #pragma unroll
        for (int i = 0; i < 8; i++)
            #pragma unroll
            for (int j = 0; j < 8; j++) acc[i][j] += xv[i]*pv[j];
    }
    __syncthreads();   // ss_s ready for all

    #pragma unroll
    for (int i = 0; i < 8; i++){
        int r = ri*8 + i;
        float mx = -3.0e38f;
        #pragma unroll
        for (int j = 0; j < 8; j++){ acc[i][j] *= NORMC; mx = fmaxf(mx, acc[i][j]); }
        #pragma unroll
        for (int o = 16; o > 0; o >>= 1) mx = fmaxf(mx, __shfl_xor_sync(0xffffffffu, mx, o));

        int grow = row0 + r;            // (b*L + l)*H + h
        int hh = grow & 7;
        int bl = grow >> 3;             // b*L + l
        int b  = bl >> 11;              // /2048
        int l  = bl & 2047;
        int bh = b*Hc + hh;
        float diag = DIAGC * ss_s[r];
        size_t drow = ((size_t)bh*Lc + l)*Mc + mi*8;

        if (isQuery){
            float o_[8];
            #pragma unroll
            for (int j = 0; j < 8; j++)
                o_[j] = RATIO * (__expf(acc[i][j] - diag - mx) + KEPS);
            *(float4*)&g_qp[drow]     = make_float4(o_[0],o_[1],o_[2],o_[3]);
            *(float4*)&g_qp[drow + 4] = make_float4(o_[4],o_[5],o_[6],o_[7]);
        } else {
            *(float4*)&g_kdash[drow]     = make_float4(acc[i][0],acc[i][1],acc[i][2],acc[i][3]);
            *(float4*)&g_kdash[drow + 4] = make_float4(acc[i][4],acc[i][5],acc[i][6],acc[i][7]);
            if (mi == 0){
                g_kdiag[bh*Lc + l] = diag;
                atomicMaxF(&g_kmax[bh], mx);
            }
        }
    }
}

// ============================================================
// K3: per-chunk key exp + state  S_c = K'^T V  (256x64), z_c = sum K'
// ============================================================
__global__ __launch_bounds__(256) void state_kernel(const float* __restrict__ V)
{
    extern __shared__ float sm[];
    float* kp_s = sm;                 // [64][256]
    float* v_s  = kp_s + CHUNK*Mc;    // [64][64]
    const int tid = threadIdx.x;
    const int bh = blockIdx.x >> 5, c = blockIdx.x & 31;
    const int b = bh >> 3, h = bh & 7;
    const float kmaxv = g_kmax[bh];
    const int lbase = c*CHUNK;
    const size_t base_lm = ((size_t)bh*Lc + lbase)*Mc;

    for (int i = tid; i < CHUNK*Mc; i += 256){
        int t = i >> 8;
        float dash = g_kdash[base_lm + i];
        float kd   = g_kdiag[bh*Lc + lbase + t];
        float val  = RATIO * (__expf(dash - kd - kmaxv) + KEPS);
        kp_s[i] = val;
        g_kp[base_lm + i] = val;
    }
    const size_t vbase = (((size_t)b*Lc + lbase)*Hc + h)*Dc;
    for (int i = tid; i < CHUNK*Dc; i += 256){
        int t = i >> 6, d = i & 63;
        v_s[i] = V[vbase + (size_t)t*(Hc*Dc) + d];
    }
    __syncthreads();

    const int a = tid >> 3, bq = tid & 7;   // m rows a*8.., d cols bq*8..
    float acc[8][8];
    #pragma unroll
    for (int i = 0; i < 8; i++)
        #pragma unroll
        for (int j = 0; j < 8; j++) acc[i][j] = 0.f;

    #pragma unroll 4
    for (int t = 0; t < CHUNK; t++){
        float4 k0 = *(const float4*)&kp_s[t*Mc + a*8];
        float4 k1 = *(const float4*)&kp_s[t*Mc + a*8 + 4];
        float4 v0 = *(const float4*)&v_s[t*Dc + bq*8];
        float4 v1 = *(const float4*)&v_s[t*Dc + bq*8 + 4];
        float kf[8] = {k0.x,k0.y,k0.z,k0.w,k1.x,k1.y,k1.z,k1.w};
        float vf[8] = {v0.x,v0.y,v0.z,v0.w,v1.x,v1.y,v1.z,v1.w};
        #pragma unroll
        for (int i = 0; i < 8; i++)
            #pragma unroll
            for (int j = 0; j < 8; j++) acc[i][j] += kf[i]*vf[j];
    }

    float zv = 0.f;
    #pragma unroll 8
    for (int t = 0; t < CHUNK; t++) zv += kp_s[t*Mc + tid];

    const size_t Sbase = ((size_t)bh*NCH + c)*Mc*Dc;
    #pragma unroll
    for (int im = 0; im < 8; im++){
        size_t o = Sbase + (size_t)(a*8 + im)*Dc + bq*8;
        *(float4*)&g_S[o]     = make_float4(acc[im][0],acc[im][1],acc[im][2],acc[im][3]);
        *(float4*)&g_S[o + 4] = make_float4(acc[im][4],acc[im][5],acc[im][6],acc[im][7]);
    }
    g_z[((size_t)bh*NCH + c)*Mc + tid] = zv;
}

// ============================================================
// K4: exclusive prefix over chunks (in place) for S and z
// ============================================================
__global__ __launch_bounds__(256) void prefix_kernel()
{
    const int bh = blockIdx.x >> 3, sl = blockIdx.x & 7;
    const int tid = threadIdx.x;
    size_t base = (size_t)bh*NCH*Mc*Dc;
    for (int e = sl*2048 + tid; e < (sl+1)*2048; e += 256){
        float run = 0.f; size_t idx = base + e;
        #pragma unroll 8
        for (int c2 = 0; c2 < NCH; c2++){
            float tmp = g_S[idx]; g_S[idx] = run; run += tmp; idx += (size_t)Mc*Dc;
        }
    }
    if (sl == 0){
        size_t zb = (size_t)bh*NCH*Mc;
        float run = 0.f; size_t idx = zb + tid;
        #pragma unroll 8
        for (int c2 = 0; c2 < NCH; c2++){
            float tmp = g_z[idx]; g_z[idx] = run; run += tmp; idx += Mc;
        }
    }
}

// ============================================================
// K5: per-chunk output:
//   A = Q'K'^T (causal), num = A V + Q' S_pre, den = rowsum(A) + Q' z_pre
// ============================================================
#define TS 68
__global__ __launch_bounds__(256) void out_kernel(const float* __restrict__ V,
                                                  float* __restrict__ Out)
{
    extern __shared__ float sm[];
    float* qT    = sm;                  // [256][TS]  q' transposed (m, t)
    float* kT    = qT + Mc*TS;          // [256][TS]  k' transposed (m, t) -> reused as S (m, d)
    float* v_s   = kT + Mc*TS;          // [64][TS]   (s, d)
    float* A_T   = v_s + CHUNK*TS;      // [64][TS]   A transposed (s, t)
    float* z_s   = A_T + CHUNK*TS;      // [256]
    float* den_s = z_s + Mc;            // [64]
    const int tid = threadIdx.x;
    const int bh = blockIdx.x >> 5, c = blockIdx.x & 31;
    const int b = bh >> 3, h = bh & 7;
    const int lbase = c*CHUNK;

    const size_t qbase = ((size_t)bh*Lc + lbase)*Mc;
    for (int i = tid; i < CHUNK*Mc; i += 256){
        int t = i >> 8, m = i & 255;
        qT[m*TS + t] = g_qp[qbase + i];
        kT[m*TS + t] = g_kp[qbase + i];
    }
    const size_t vbase = (((size_t)b*Lc + lbase)*Hc + h)*Dc;
    for (int i = tid; i < CHUNK*Dc; i += 256){
        int t = i >> 6, d = i & 63;
        v_s[t*TS + d] = V[vbase + (size_t)t*(Hc*Dc) + d];
    }
    __syncthreads();

    const int ti = tid >> 4, si = tid & 15;   // t rows ti*4.., s/d cols si*4..

    // ---- Phase A: A = Q' K'^T over m ----
    float accA[4][4];
    #pragma unroll
    for (int i = 0; i < 4; i++)
        #pragma unroll
        for (int j = 0; j < 4; j++) accA[i][j] = 0.f;

    #pragma unroll 8
    for (int m = 0; m < Mc; m++){
        float4 qf = *(const float4*)&qT[m*TS + ti*4];
        float4 kf = *(const float4*)&kT[m*TS + si*4];
        float qv[4] = {qf.x,qf.y,qf.z,qf.w};
        float kv[4] = {kf.x,kf.y,kf.z,kf.w};
        #pragma unroll
        for (int i = 0; i < 4; i++)
            #pragma unroll
            for (int j = 0; j < 4; j++) accA[i][j] += qv[i]*kv[j];
    }

    // mask (s<=t), store A^T, row-sum -> den_s (16-lane reduce, si==0 writes)
    #pragma unroll
    for (int i = 0; i < 4; i++){
        int t = ti*4 + i;
        float dp = 0.f;
        #pragma unroll
        for (int j = 0; j < 4; j++){
            int s = si*4 + j;
            float val = (s <= t) ? accA[i][j] : 0.f;
            A_T[s*TS + t] = val;
            dp += val;
        }
        #pragma unroll
        for (int o = 8; o > 0; o >>= 1) dp += __shfl_xor_sync(0xffffffffu, dp, o);
        if (si == 0) den_s[t] = dp;
    }
    __syncthreads();

    // ---- load prefix state into kT region; z ----
    const size_t Sb = ((size_t)bh*NCH + c)*Mc*Dc;
    for (int i = tid; i < Mc*Dc; i += 256){
        int m = i >> 6, d = i & 63;
        kT[m*TS + d] = g_S[Sb + i];
    }
    z_s[tid] = g_z[((size_t)bh*NCH + c)*Mc + tid];
    __syncthreads();

    // den_inter: den[t] += sum_m q'[t][m] z[m]
    if (tid < 64){
        float s2 = 0.f;
        #pragma unroll 8
        for (int m = 0; m < Mc; m++) s2 += qT[m*TS + tid] * z_s[m];
        den_s[tid] += s2;
    }

    // ---- Phase B: num = Q' S_pre + A V ----
    float accB[4][4];
    #pragma unroll
    for (int i = 0; i < 4; i++)
        #pragma unroll
        for (int j = 0; j < 4; j++) accB[i][j] = 0.f;

    #pragma unroll 8
    for (int m = 0; m < Mc; m++){
        float4 qf = *(const float4*)&qT[m*TS + ti*4];
        float4 sf = *(const float4*)&kT[m*TS + si*4];
        float qv[4] = {qf.x,qf.y,qf.z,qf.w};
        float sv[4] = {sf.x,sf.y,sf.z,sf.w};
        #pragma unroll
        for (int i = 0; i < 4; i++)
            #pragma unroll
            for (int j = 0; j < 4; j++) accB[i][j] += qv[i]*sv[j];
    }
    #pragma unroll 4
    for (int s = 0; s < CHUNK; s++){
        float4 af = *(const float4*)&A_T[s*TS + ti*4];
        float4 vf = *(const float4*)&v_s[s*TS + si*4];
        float av[4] = {af.x,af.y,af.z,af.w};
        float vv[4] = {vf.x,vf.y,vf.z,vf.w};
        #pragma unroll
        for (int i = 0; i < 4; i++)
            #pragma unroll
            for (int j = 0; j < 4; j++) accB[i][j] += av[i]*vv[j];
    }
    __syncthreads();   // den_s complete

    const size_t obase = (((size_t)b*Lc + lbase)*Hc + h)*Dc;
    #pragma unroll
    for (int i = 0; i < 4; i++){
        int t = ti*4 + i;
        float den = den_s[t];
        if (fabsf(den) <= 1e-6f) den += 2e-6f;
        float inv = 1.0f / den;
        float4 o4 = make_float4(accB[i][0]*inv, accB[i][1]*inv,
                                accB[i][2]*inv, accB[i][3]*inv);
        *(float4*)&Out[obase + (size_t)t*(Hc*Dc) + si*4] = o4;
    }
}

// ============================================================
extern "C" void kernel_launch(void* const* d_in, const int* in_sizes, int n_in,
                              void* d_out, int out_size)
{
    const float* Q = (const float*)d_in[0];
    const float* K = (const float*)d_in[1];
    const float* V = (const float*)d_in[2];
    const float* P = (const float*)d_in[3];
    float* O = (float*)d_out;

    const int SM1 = (64*PT_S + 64*XT_S + 64) * 4;                 // ~84 KB
    const int SM3 = (CHUNK*Mc + CHUNK*Dc) * 4;                    // 80 KB
    const int SM5 = (Mc*TS*2 + CHUNK*TS*2 + Mc + 64) * 4;         // ~175 KB

    cudaFuncSetAttribute(feat_kernel,  cudaFuncAttributeMaxDynamicSharedMemorySize, SM1);
    cudaFuncSetAttribute(state_kernel, cudaFuncAttributeMaxDynamicSharedMemorySize, SM3);
    cudaFuncSetAttribute(out_kernel,   cudaFuncAttributeMaxDynamicSharedMemorySize, SM5);

    init_kernel<<<1, 32>>>();
    feat_kernel<<<NROWS/64, 256, SM1>>>(Q, P, 1);
    feat_kernel<<<NROWS/64, 256, SM1>>>(K, P, 0);
    state_kernel<<<BH*NCH, 256, SM3>>>(V);
    prefix_kernel<<<BH*8, 256>>>();
    out_kernel<<<BH*NCH, 256, SM5>>>(V, O);
}

// round 3
// speedup vs baseline: 1.0057x; 1.0057x over previous
#include <cuda_runtime.h>
#include <math.h>

// Problem dims (fixed for this problem instance)
#define Bc 4
#define Lc 2048
#define Hc 8
#define Dc 64
#define Mc 256
#define CHUNK 64
#define NCH (Lc/CHUNK)       // 32
#define BH (Bc*Hc)           // 32
#define NROWS (Bc*Lc*Hc)     // 65536

#define NORMC 0.35355339059327373f   // 64^(-1/4)
#define RATIO 0.0625f                // 1/sqrt(256)
#define DIAGC 0.0625f                // 0.5 * 64^(-1/2)
#define KEPS  1e-4f

// ----- scratch (static device arrays; no allocation) -----
__device__ float g_qp   [(size_t)BH*Lc*Mc];   // 64 MB  [bh][l][m] query features
__device__ float g_kdash[(size_t)BH*Lc*Mc];   // 64 MB  raw key dash
__device__ float g_kp   [(size_t)BH*Lc*Mc];   // 64 MB  key features
__device__ float g_kdiag[BH*Lc];
__device__ float g_kmax [BH];
__device__ float g_S    [(size_t)BH*NCH*Mc*Dc]; // 64 MB  chunk states -> exclusive prefix
__device__ float g_z    [(size_t)BH*NCH*Mc];

__device__ __forceinline__ void atomicMaxF(float* addr, float v){
    int old = __float_as_int(*addr);
    while (__int_as_float(old) < v){
        int assumed = old;
        old = atomicCAS((int*)addr, assumed, __float_as_int(v));
        if (old == assumed) break;
    }
}

__global__ void init_kernel(){
    if (threadIdx.x < BH) g_kmax[threadIdx.x] = -3.0e38f;
}

// ============================================================
// K1: features. X:[B,L,H,D] -> dash = norm * X @ P^T  (rows = b*L*H+l*H+h)
// queries: full feature (row-max stab), keys: store raw dash + diag + bh-max
// ============================================================
#define PT_S 260
#define XT_S 68

__global__ __launch_bounds__(256) void feat_kernel(const float* __restrict__ X,
                                                   const float* __restrict__ P,
                                                   int isQuery)
{
    extern __shared__ float sm[];
    float* Pt   = sm;                 // [64][PT_S] transposed projection
    float* xT   = Pt + 64*PT_S;       // [64][XT_S] transposed x rows
    float* ss_s = xT + 64*XT_S;       // [64] sum of squares per row
    const int tid = threadIdx.x;

    for (int i = tid; i < Mc*Dc; i += 256){
        int m = i >> 6, d = i & 63;
        Pt[d*PT_S + m] = P[i];
    }
    const int row0 = blockIdx.x * 64;
    const float* Xb = X + (size_t)row0 * Dc;
    for (int i = tid; i < 64*Dc; i += 256){
        int r = i >> 6, d = i & 63;
        xT[d*XT_S + r] = Xb[i];
    }
    __syncthreads();

    if (tid < 64){
        float s = 0.f;
        #pragma unroll
        for (int d = 0; d < 64; d++){ float xv = xT[d*XT_S + tid]; s += xv*xv; }
        ss_s[tid] = s;
    }

    const int ri = tid >> 5, mi = tid & 31;   // warp = ri, rows ri*8.., cols mi*8..
    float acc[8][8];
    #pragma unroll
    for (int i = 0; i < 8; i++)
        #pragma unroll
        for (int j = 0; j < 8; j++) acc[i][j] = 0.f;

    #pragma unroll 4
    for (int d = 0; d < 64; d++){
        float4 x0 = *(const float4*)&xT[d*XT_S + ri*8];
        float4 x1 = *(const float4*)&xT[d*XT_S + ri*8 + 4];
        float4 p0 = *(const float4*)&Pt[d*PT_S + mi*8];
        float4 p1 = *(const float4*)&Pt[d*PT_S + mi*8 + 4];
        float xv[8] = {x0.x,x0.y,x0.z,x0.w,x1.x,x1.y,x1.z,x1.w};
        float pv[8] = {p0.x,p0.y,p0.z,p0.w,p1.x,p1.y,p1.z,p1.w};
        #pragma unroll
        for (int i = 0; i < 8; i++)
            #pragma unroll
            for (int j = 0; j < 8; j++) acc[i][j] += xv[i]*pv[j];
    }
    __syncthreads();   // ss_s ready for all

    #pragma unroll
    for (int i = 0; i < 8; i++){
        int r = ri*8 + i;
        float mx = -3.0e38f;
        #pragma unroll
        for (int j = 0; j < 8; j++){ acc[i][j] *= NORMC; mx = fmaxf(mx, acc[i][j]); }
        #pragma unroll
        for (int o = 16; o > 0; o >>= 1) mx = fmaxf(mx, __shfl_xor_sync(0xffffffffu, mx, o));

        int grow = row0 + r;            // (b*L + l)*H + h
        int hh = grow & 7;
        int bl = grow >> 3;             // b*L + l
        int b  = bl >> 11;              // /2048
        int l  = bl & 2047;
        int bh = b*Hc + hh;
        float diag = DIAGC * ss_s[r];
        size_t drow = ((size_t)bh*Lc + l)*Mc + mi*8;

        if (isQuery){
            float o_[8];
            #pragma unroll
            for (int j = 0; j < 8; j++)
                o_[j] = RATIO * (__expf(acc[i][j] - diag - mx) + KEPS);
            *(float4*)&g_qp[drow]     = make_float4(o_[0],o_[1],o_[2],o_[3]);
            *(float4*)&g_qp[drow + 4] = make_float4(o_[4],o_[5],o_[6],o_[7]);
        } else {
            *(float4*)&g_kdash[drow]     = make_float4(acc[i][0],acc[i][1],acc[i][2],acc[i][3]);
            *(float4*)&g_kdash[drow + 4] = make_float4(acc[i][4],acc[i][5],acc[i][6],acc[i][7]);
            if (mi == 0){
                g_kdiag[bh*Lc + l] = diag;
                atomicMaxF(&g_kmax[bh], mx);
            }
        }
    }
}

// ============================================================
// K3: per-chunk key exp + state  S_c = K'^T V  (256x64), z_c = sum K'
// ============================================================
__global__ __launch_bounds__(256) void state_kernel(const float* __restrict__ V)
{
    extern __shared__ float sm[];
    float* kp_s = sm;                 // [64][256]
    float* v_s  = kp_s + CHUNK*Mc;    // [64][64]
    const int tid = threadIdx.x;
    const int bh = blockIdx.x >> 5, c = blockIdx.x & 31;
    const int b = bh >> 3, h = bh & 7;
    const float kmaxv = g_kmax[bh];
    const int lbase = c*CHUNK;
    const size_t base_lm = ((size_t)bh*Lc + lbase)*Mc;

    for (int i = tid; i < CHUNK*Mc; i += 256){
        int t = i >> 8;
        float dash = g_kdash[base_lm + i];
        float kd   = g_kdiag[bh*Lc + lbase + t];
        float val  = RATIO * (__expf(dash - kd - kmaxv) + KEPS);
        kp_s[i] = val;
        g_kp[base_lm + i] = val;
    }
    const size_t vbase = (((size_t)b*Lc + lbase)*Hc + h)*Dc;
    for (int i = tid; i < CHUNK*Dc; i += 256){
        int t = i >> 6, d = i & 63;
        v_s[i] = V[vbase + (size_t)t*(Hc*Dc) + d];
    }
    __syncthreads();

    const int a = tid >> 3, bq = tid & 7;   // m rows a*8.., d cols bq*8..
    float acc[8][8];
    #pragma unroll
    for (int i = 0; i < 8; i++)
        #pragma unroll
        for (int j = 0; j < 8; j++) acc[i][j] = 0.f;

    #pragma unroll 4
    for (int t = 0; t < CHUNK; t++){
        float4 k0 = *(const float4*)&kp_s[t*Mc + a*8];
        float4 k1 = *(const float4*)&kp_s[t*Mc + a*8 + 4];
        float4 v0 = *(const float4*)&v_s[t*Dc + bq*8];
        float4 v1 = *(const float4*)&v_s[t*Dc + bq*8 + 4];
        float kf[8] = {k0.x,k0.y,k0.z,k0.w,k1.x,k1.y,k1.z,k1.w};
        float vf[8] = {v0.x,v0.y,v0.z,v0.w,v1.x,v1.y,v1.z,v1.w};
        #pragma unroll
        for (int i = 0; i < 8; i++)
            #pragma unroll
            for (int j = 0; j < 8; j++) acc[i][j] += kf[i]*vf[j];
    }

    float zv = 0.f;
    #pragma unroll 8
    for (int t = 0; t < CHUNK; t++) zv += kp_s[t*Mc + tid];

    const size_t Sbase = ((size_t)bh*NCH + c)*Mc*Dc;
    #pragma unroll
    for (int im = 0; im < 8; im++){
        size_t o = Sbase + (size_t)(a*8 + im)*Dc + bq*8;
        *(float4*)&g_S[o]     = make_float4(acc[im][0],acc[im][1],acc[im][2],acc[im][3]);
        *(float4*)&g_S[o + 4] = make_float4(acc[im][4],acc[im][5],acc[im][6],acc[im][7]);
    }
    g_z[((size_t)bh*NCH + c)*Mc + tid] = zv;
}

// ============================================================
// K4: exclusive prefix over chunks (in place) for S and z
// ============================================================
__global__ __launch_bounds__(256) void prefix_kernel()
{
    const int bh = blockIdx.x >> 3, sl = blockIdx.x & 7;
    const int tid = threadIdx.x;
    size_t base = (size_t)bh*NCH*Mc*Dc;
    for (int e = sl*2048 + tid; e < (sl+1)*2048; e += 256){
        float run = 0.f; size_t idx = base + e;
        #pragma unroll 8
        for (int c2 = 0; c2 < NCH; c2++){
            float tmp = g_S[idx]; g_S[idx] = run; run += tmp; idx += (size_t)Mc*Dc;
        }
    }
    if (sl == 0){
        size_t zb = (size_t)bh*NCH*Mc;
        float run = 0.f; size_t idx = zb + tid;
        #pragma unroll 8
        for (int c2 = 0; c2 < NCH; c2++){
            float tmp = g_z[idx]; g_z[idx] = run; run += tmp; idx += Mc;
        }
    }
}

// ============================================================
// K5: per-chunk output:
//   A = Q'K'^T (causal), num = A V + Q' S_pre, den = rowsum(A) + Q' z_pre
// ============================================================
#define TS 68
__global__ __launch_bounds__(256) void out_kernel(const float* __restrict__ V,
                                                  float* __restrict__ Out)
{
    extern __shared__ float sm[];
    float* qT    = sm;                  // [256][TS]  q' transposed (m, t)
    float* kT    = qT + Mc*TS;          // [256][TS]  k' transposed (m, t) -> reused as S (m, d)
    float* v_s   = kT + Mc*TS;          // [64][TS]   (s, d)
    float* A_T   = v_s + CHUNK*TS;      // [64][TS]   A transposed (s, t)
    float* z_s   = A_T + CHUNK*TS;      // [256]
    float* den_s = z_s + Mc;            // [64]
    const int tid = threadIdx.x;
    const int bh = blockIdx.x >> 5, c = blockIdx.x & 31;
    const int b = bh >> 3, h = bh & 7;
    const int lbase = c*CHUNK;

    const size_t qbase = ((size_t)bh*Lc + lbase)*Mc;
    for (int i = tid; i < CHUNK*Mc; i += 256){
        int t = i >> 8, m = i & 255;
        qT[m*TS + t] = g_qp[qbase + i];
        kT[m*TS + t] = g_kp[qbase + i];
    }
    const size_t vbase = (((size_t)b*Lc + lbase)*Hc + h)*Dc;
    for (int i = tid; i < CHUNK*Dc; i += 256){
        int t = i >> 6, d = i & 63;
        v_s[t*TS + d] = V[vbase + (size_t)t*(Hc*Dc) + d];
    }
    __syncthreads();

    const int ti = tid >> 4, si = tid & 15;   // t rows ti*4.., s/d cols si*4..

    // ---- Phase A: A = Q' K'^T over m ----
    float accA[4][4];
    #pragma unroll
    for (int i = 0; i < 4; i++)
        #pragma unroll
        for (int j = 0; j < 4; j++) accA[i][j] = 0.f;

    #pragma unroll 8
    for (int m = 0; m < Mc; m++){
        float4 qf = *(const float4*)&qT[m*TS + ti*4];
        float4 kf = *(const float4*)&kT[m*TS + si*4];
        float qv[4] = {qf.x,qf.y,qf.z,qf.w};
        float kv[4] = {kf.x,kf.y,kf.z,kf.w};
        #pragma unroll
        for (int i = 0; i < 4; i++)
            #pragma unroll
            for (int j = 0; j < 4; j++) accA[i][j] += qv[i]*kv[j];
    }

    // mask (s<=t), store A^T, row-sum -> den_s (16-lane reduce, si==0 writes)
    #pragma unroll
    for (int i = 0; i < 4; i++){
        int t = ti*4 + i;
        float dp = 0.f;
        #pragma unroll
        for (int j = 0; j < 4; j++){
            int s = si*4 + j;
            float val = (s <= t) ? accA[i][j] : 0.f;
            A_T[s*TS + t] = val;
            dp += val;
        }
        #pragma unroll
        for (int o = 8; o > 0; o >>= 1) dp += __shfl_xor_sync(0xffffffffu, dp, o);
        if (si == 0) den_s[t] = dp;
    }
    __syncthreads();

    // ---- load prefix state into kT region; z ----
    const size_t Sb = ((size_t)bh*NCH + c)*Mc*Dc;
    for (int i = tid; i < Mc*Dc; i += 256){
        int m = i >> 6, d = i & 63;
        kT[m*TS + d] = g_S[Sb + i];
    }
    z_s[tid] = g_z[((size_t)bh*NCH + c)*Mc + tid];
    __syncthreads();

    // den_inter: den[t] += sum_m q'[t][m] z[m]
    if (tid < 64){
        float s2 = 0.f;
        #pragma unroll 8
        for (int m = 0; m < Mc; m++) s2 += qT[m*TS + tid] * z_s[m];
        den_s[tid] += s2;
    }

    // ---- Phase B: num = Q' S_pre + A V ----
    float accB[4][4];
    #pragma unroll
    for (int i = 0; i < 4; i++)
        #pragma unroll
        for (int j = 0; j < 4; j++) accB[i][j] = 0.f;

    #pragma unroll 8
    for (int m = 0; m < Mc; m++){
        float4 qf = *(const float4*)&qT[m*TS + ti*4];
        float4 sf = *(const float4*)&kT[m*TS + si*4];
        float qv[4] = {qf.x,qf.y,qf.z,qf.w};
        float sv[4] = {sf.x,sf.y,sf.z,sf.w};
        #pragma unroll
        for (int i = 0; i < 4; i++)
            #pragma unroll
            for (int j = 0; j < 4; j++) accB[i][j] += qv[i]*sv[j];
    }
    #pragma unroll 4
    for (int s = 0; s < CHUNK; s++){
        float4 af = *(const float4*)&A_T[s*TS + ti*4];
        float4 vf = *(const float4*)&v_s[s*TS + si*4];
        float av[4] = {af.x,af.y,af.z,af.w};
        float vv[4] = {vf.x,vf.y,vf.z,vf.w};
        #pragma unroll
        for (int i = 0; i < 4; i++)
            #pragma unroll
            for (int j = 0; j < 4; j++) accB[i][j] += av[i]*vv[j];
    }
    __syncthreads();   // den_s complete

    const size_t obase = (((size_t)b*Lc + lbase)*Hc + h)*Dc;
    #pragma unroll
    for (int i = 0; i < 4; i++){
        int t = ti*4 + i;
        float den = den_s[t];
        if (fabsf(den) <= 1e-6f) den += 2e-6f;
        float inv = 1.0f / den;
        float4 o4 = make_float4(accB[i][0]*inv, accB[i][1]*inv,
                                accB[i][2]*inv, accB[i][3]*inv);
        *(float4*)&Out[obase + (size_t)t*(Hc*Dc) + si*4] = o4;
    }
}

// ============================================================
extern "C" void kernel_launch(void* const* d_in, const int* in_sizes, int n_in,
                              void* d_out, int out_size)
{
    const float* Q = (const float*)d_in[0];
    const float* K = (const float*)d_in[1];
    const float* V = (const float*)d_in[2];
    const float* P = (const float*)d_in[3];
    float* O = (float*)d_out;

    const int SM1 = (64*PT_S + 64*XT_S + 64) * 4;                 // ~84 KB
    const int SM3 = (CHUNK*Mc + CHUNK*Dc) * 4;                    // 80 KB
    const int SM5 = (Mc*TS*2 + CHUNK*TS*2 + Mc + 64) * 4;         // ~175 KB

    cudaFuncSetAttribute(feat_kernel,  cudaFuncAttributeMaxDynamicSharedMemorySize, SM1);
    cudaFuncSetAttribute(state_kernel, cudaFuncAttributeMaxDynamicSharedMemorySize, SM3);
    cudaFuncSetAttribute(out_kernel,   cudaFuncAttributeMaxDynamicSharedMemorySize, SM5);

    init_kernel<<<1, 32>>>();
    feat_kernel<<<NROWS/64, 256, SM1>>>(Q, P, 1);
    feat_kernel<<<NROWS/64, 256, SM1>>>(K, P, 0);
    state_kernel<<<BH*NCH, 256, SM3>>>(V);
    prefix_kernel<<<BH*8, 256>>>();
    out_kernel<<<BH*NCH, 256, SM5>>>(V, O);
}

// round 5
// speedup vs baseline: 1.0080x; 1.0023x over previous
#include <cuda_runtime.h>
#include <math.h>

// Problem dims (fixed)
#define Bc 4
#define Lc 2048
#define Hc 8
#define Dc 64
#define Mc 256
#define CH2 128
#define NC2 (Lc/CH2)         // 16
#define BH (Bc*Hc)           // 32
#define NROWS (Bc*Lc*Hc)     // 65536

#define NORMC 0.35355339059327373f   // 64^(-1/4)
#define RATIO 0.0625f                // 1/sqrt(256)
#define DIAGC 0.0625f                // 0.5 * 64^(-1/2)
#define KEPS  1e-4f

// ----- scratch (static device arrays; no allocation) -----
__device__ float g_qp   [(size_t)BH*Lc*Mc];     // 64 MB [bh][l][m]
__device__ float g_kdash[(size_t)BH*Lc*Mc];     // 64 MB raw key dash
__device__ float g_kp   [(size_t)BH*Lc*Mc];     // 64 MB key features
__device__ float g_kdiag[BH*Lc];
__device__ float g_kmax [BH];
__device__ float g_S    [(size_t)BH*NC2*Mc*Dc]; // 32 MB chunk states -> excl prefix
__device__ float g_z    [(size_t)BH*NC2*Mc];

__device__ __forceinline__ void atomicMaxF(float* addr, float v){
    int old = __float_as_int(*addr);
    while (__int_as_float(old) < v){
        int assumed = old;
        old = atomicCAS((int*)addr, assumed, __float_as_int(v));
        if (old == assumed) break;
    }
}

__global__ void init_kernel(){
    if (threadIdx.x < BH) g_kmax[threadIdx.x] = -3.0e38f;
}

// ============================================================
// K1: features. X:[B,L,H,D] -> dash = norm * X @ P^T
// queries: full feature (row-max stab), keys: raw dash + diag + bh-max
// ============================================================
#define PT_S 260
#define XT_S 68

__global__ __launch_bounds__(256) void feat_kernel(const float* __restrict__ X,
                                                   const float* __restrict__ P,
                                                   int isQuery)
{
    extern __shared__ float sm[];
    float* Pt   = sm;                 // [64][PT_S]
    float* xT   = Pt + 64*PT_S;       // [64][XT_S]
    float* ss_s = xT + 64*XT_S;       // [64]
    const int tid = threadIdx.x;

    for (int i = tid; i < Mc*Dc; i += 256){
        int m = i >> 6, d = i & 63;
        Pt[d*PT_S + m] = P[i];
    }
    const int row0 = blockIdx.x * 64;
    const float* Xb = X + (size_t)row0 * Dc;
    for (int i = tid; i < 64*Dc; i += 256){
        int r = i >> 6, d = i & 63;
        xT[d*XT_S + r] = Xb[i];
    }
    __syncthreads();

    if (tid < 64){
        float s = 0.f;
        #pragma unroll
        for (int d = 0; d < 64; d++){ float xv = xT[d*XT_S + tid]; s += xv*xv; }
        ss_s[tid] = s;
    }

    const int ri = tid >> 5, mi = tid & 31;
    float acc[8][8];
    #pragma unroll
    for (int i = 0; i < 8; i++)
        #pragma unroll
        for (int j = 0; j < 8; j++) acc[i][j] = 0.f;

    #pragma unroll 4
    for (int d = 0; d < 64; d++){
        float4 x0 = *(const float4*)&xT[d*XT_S + ri*8];
        float4 x1 = *(const float4*)&xT[d*XT_S + ri*8 + 4];
        float4 p0 = *(const float4*)&Pt[d*PT_S + mi*4];
        float4 p1 = *(const float4*)&Pt[d*PT_S + 128 + mi*4];
        float xv[8] = {x0.x,x0.y,x0.z,x0.w,x1.x,x1.y,x1.z,x1.w};
        float pv[8] = {p0.x,p0.y,p0.z,p0.w,p1.x,p1.y,p1.z,p1.w};
        #pragma unroll
        for (int i = 0; i < 8; i++)
            #pragma unroll
            for (int j = 0; j < 8; j++) acc[i][j] += xv[i]*pv[j];
    }
    __syncthreads();

    #pragma unroll
    for (int i = 0; i < 8; i++){
        int r = ri*8 + i;
        float mx = -3.0e38f;
        #pragma unroll
        for (int j = 0; j < 8; j++){ acc[i][j] *= NORMC; mx = fmaxf(mx, acc[i][j]); }
        #pragma unroll
        for (int o = 16; o > 0; o >>= 1) mx = fmaxf(mx, __shfl_xor_sync(0xffffffffu, mx, o));

        int grow = row0 + r;
        int hh = grow & 7;
        int bl = grow >> 3;
        int b  = bl >> 11;
        int l  = bl & 2047;
        int bh = b*Hc + hh;
        float diag = DIAGC * ss_s[r];
        size_t drow = ((size_t)bh*Lc + l)*Mc;

        if (isQuery){
            float o0[4], o1[4];
            #pragma unroll
            for (int j = 0; j < 4; j++){
                o0[j] = RATIO * (__expf(acc[i][j]   - diag - mx) + KEPS);
                o1[j] = RATIO * (__expf(acc[i][j+4] - diag - mx) + KEPS);
            }
            *(float4*)&g_qp[drow + mi*4]       = make_float4(o0[0],o0[1],o0[2],o0[3]);
            *(float4*)&g_qp[drow + 128 + mi*4] = make_float4(o1[0],o1[1],o1[2],o1[3]);
        } else {
            *(float4*)&g_kdash[drow + mi*4]       = make_float4(acc[i][0],acc[i][1],acc[i][2],acc[i][3]);
            *(float4*)&g_kdash[drow + 128 + mi*4] = make_float4(acc[i][4],acc[i][5],acc[i][6],acc[i][7]);
            if (mi == 0){
                g_kdiag[bh*Lc + l] = diag;
                atomicMaxF(&g_kmax[bh], mx);
            }
        }
    }
}

// ============================================================
// K3: per-chunk (128) key exp + state S_c = K'^T V (256x64), z_c = sum K'
// ============================================================
#define VS 68
__global__ __launch_bounds__(256) void state_kernel(const float* __restrict__ V)
{
    extern __shared__ float sm[];
    float* kp_s = sm;                 // [128][256]
    float* v_s  = kp_s + CH2*Mc;      // [128][VS]
    const int tid = threadIdx.x;
    const int bh = blockIdx.x >> 4, c = blockIdx.x & 15;
    const int b = bh >> 3, h = bh & 7;
    const float kmaxv = g_kmax[bh];
    const int lbase = c*CH2;
    const size_t base_lm = ((size_t)bh*Lc + lbase)*Mc;

    for (int i = tid; i < CH2*Mc; i += 256){
        int t = i >> 8;
        float dash = g_kdash[base_lm + i];
        float kd   = g_kdiag[bh*Lc + lbase + t];
        float val  = RATIO * (__expf(dash - kd - kmaxv) + KEPS);
        kp_s[i] = val;
        g_kp[base_lm + i] = val;
    }
    const size_t vbase = (((size_t)b*Lc + lbase)*Hc + h)*Dc;
    for (int i = tid; i < CH2*Dc; i += 256){
        int t = i >> 6, d = i & 63;
        v_s[t*VS + d] = V[vbase + (size_t)t*(Hc*Dc) + d];
    }
    __syncthreads();

    // m rows a*8.., d cols split {bq*4, 32+bq*4}
    const int a = tid >> 3, bq = tid & 7;
    float acc[8][8];
    #pragma unroll
    for (int i = 0; i < 8; i++)
        #pragma unroll
        for (int j = 0; j < 8; j++) acc[i][j] = 0.f;

    #pragma unroll 4
    for (int t = 0; t < CH2; t++){
        float4 k0 = *(const float4*)&kp_s[t*Mc + a*8];
        float4 k1 = *(const float4*)&kp_s[t*Mc + a*8 + 4];
        float4 v0 = *(const float4*)&v_s[t*VS + bq*4];
        float4 v1 = *(const float4*)&v_s[t*VS + 32 + bq*4];
        float kf[8] = {k0.x,k0.y,k0.z,k0.w,k1.x,k1.y,k1.z,k1.w};
        float vf[8] = {v0.x,v0.y,v0.z,v0.w,v1.x,v1.y,v1.z,v1.w};
        #pragma unroll
        for (int i = 0; i < 8; i++)
            #pragma unroll
            for (int j = 0; j < 8; j++) acc[i][j] += kf[i]*vf[j];
    }

    float zv = 0.f;
    #pragma unroll 8
    for (int t = 0; t < CH2; t++) zv += kp_s[t*Mc + tid];

    const size_t Sbase = ((size_t)bh*NC2 + c)*Mc*Dc;
    #pragma unroll
    for (int im = 0; im < 8; im++){
        size_t o = Sbase + (size_t)(a*8 + im)*Dc;
        *(float4*)&g_S[o + bq*4]      = make_float4(acc[im][0],acc[im][1],acc[im][2],acc[im][3]);
        *(float4*)&g_S[o + 32 + bq*4] = make_float4(acc[im][4],acc[im][5],acc[im][6],acc[im][7]);
    }
    g_z[((size_t)bh*NC2 + c)*Mc + tid] = zv;
}

// ============================================================
// K4: exclusive prefix over 16 chunks (in place) for S and z
// ============================================================
__global__ __launch_bounds__(256) void prefix_kernel()
{
    const int bh = blockIdx.x >> 3, sl = blockIdx.x & 7;
    const int tid = threadIdx.x;
    size_t base = (size_t)bh*NC2*Mc*Dc;
    for (int e = sl*2048 + tid; e < (sl+1)*2048; e += 256){
        float run = 0.f; size_t idx = base + e;
        #pragma unroll
        for (int c2 = 0; c2 < NC2; c2++){
            float tmp = g_S[idx]; g_S[idx] = run; run += tmp; idx += (size_t)Mc*Dc;
        }
    }
    if (sl == 0){
        size_t zb = (size_t)bh*NC2*Mc;
        float run = 0.f; size_t idx = zb + tid;
        #pragma unroll
        for (int c2 = 0; c2 < NC2; c2++){
            float tmp = g_z[idx]; g_z[idx] = run; run += tmp; idx += Mc;
        }
    }
}

// ============================================================
// K5: per 128-token chunk:
//  fused over m:  A = Q'K'^T (128x128), numI = Q' S_pre (128x64), denI = Q' z
//  then: mask A, den = rowsum(A)+denI, num = numI + A V, out = num/den
// thread map: ti=tid>>4 -> t rows ti*8.., si=tid&15 -> cols {si*4, 64+si*4} (A)
//             and d cols si*4 (num)
// ============================================================
#define QTS 132
#define ATS 132
__global__ __launch_bounds__(256) void out_kernel(const float* __restrict__ V,
                                                  float* __restrict__ Out)
{
    extern __shared__ float sm[];
    float* qtile = sm;                   // [32][QTS]  (m-major, t cols)
    float* ktile = qtile + 32*QTS;       // [32][QTS]
    float* Stile = ktile + 32*QTS;       // [32][VS]   (m-major, d cols)
    float* ztile = Stile + 32*VS;        // [32]
    float* A_T   = ztile + 32;           // [128][ATS] (s-major, t cols)
    float* v_s   = A_T + 128*ATS;        // [128][VS]
    float* den_s = v_s + 128*VS;         // [128]

    const int tid = threadIdx.x;
    const int bh = blockIdx.x >> 4, c = blockIdx.x & 15;
    const int b = bh >> 3, h = bh & 7;
    const int lbase = c*CH2;
    const int ti = tid >> 4, si = tid & 15;

    const size_t qbase = ((size_t)bh*Lc + lbase)*Mc;
    const size_t Sb    = ((size_t)bh*NC2 + c)*Mc*Dc;
    const size_t zb    = ((size_t)bh*NC2 + c)*Mc;
    const size_t vbase = (((size_t)b*Lc + lbase)*Hc + h)*Dc;

    // preload V tile (used in AV phase)
    for (int i = tid; i < CH2*Dc; i += 256){
        int t = i >> 6, d = i & 63;
        v_s[t*VS + d] = V[vbase + (size_t)t*(Hc*Dc) + d];
    }

    float accA[8][8];    // [t][s-split]
    float accB[8][4];    // [t][d]
    float accD[8];       // [t] den intermediate
    #pragma unroll
    for (int i = 0; i < 8; i++){
        accD[i] = 0.f;
        #pragma unroll
        for (int j = 0; j < 8; j++) accA[i][j] = 0.f;
        #pragma unroll
        for (int j = 0; j < 4; j++) accB[i][j] = 0.f;
    }

    // ---- fused m loop: 8 tiles of 32 ----
    for (int m0 = 0; m0 < Mc; m0 += 32){
        __syncthreads();
        // load q/k tiles transposed: [m][t]
        for (int i = tid; i < 32*CH2; i += 256){
            int mm = i & 31, t = i >> 5;
            qtile[mm*QTS + t] = g_qp[qbase + (size_t)t*Mc + m0 + mm];
            ktile[mm*QTS + t] = g_kp[qbase + (size_t)t*Mc + m0 + mm];
        }
        // S tile [m][d] (already m-major in global)
        for (int i = tid; i < 32*Dc; i += 256){
            int d = i & 63, mm = i >> 6;
            Stile[mm*VS + d] = g_S[Sb + (size_t)(m0+mm)*Dc + d];
        }
        if (tid < 32) ztile[tid] = g_z[zb + m0 + tid];
        __syncthreads();

        #pragma unroll 4
        for (int mm = 0; mm < 32; mm++){
            float4 q0 = *(const float4*)&qtile[mm*QTS + ti*8];
            float4 q1 = *(const float4*)&qtile[mm*QTS + ti*8 + 4];
            float4 k0 = *(const float4*)&ktile[mm*QTS + si*4];
            float4 k1 = *(const float4*)&ktile[mm*QTS + 64 + si*4];
            float4 sf = *(const float4*)&Stile[mm*VS + si*4];
            float  zv = ztile[mm];
            float qv[8] = {q0.x,q0.y,q0.z,q0.w,q1.x,q1.y,q1.z,q1.w};
            float kv[8] = {k0.x,k0.y,k0.z,k0.w,k1.x,k1.y,k1.z,k1.w};
            float sv[4] = {sf.x,sf.y,sf.z,sf.w};
            #pragma unroll
            for (int i = 0; i < 8; i++){
                #pragma unroll
                for (int j = 0; j < 8; j++) accA[i][j] += qv[i]*kv[j];
                #pragma unroll
                for (int j = 0; j < 4; j++) accB[i][j] += qv[i]*sv[j];
                accD[i] += qv[i]*zv;
            }
        }
    }
    __syncthreads();

    // ---- mask, write A^T [s][t], den row-sums ----
    #pragma unroll
    for (int j = 0; j < 8; j++){
        int s = (j < 4) ? (si*4 + j) : (64 + si*4 + (j-4));
        float w[8];
        #pragma unroll
        for (int i = 0; i < 8; i++){
            int t = ti*8 + i;
            w[i] = (s <= t) ? accA[i][j] : 0.f;
            accA[i][j] = w[i];
        }
        *(float4*)&A_T[s*ATS + ti*8]     = make_float4(w[0],w[1],w[2],w[3]);
        *(float4*)&A_T[s*ATS + ti*8 + 4] = make_float4(w[4],w[5],w[6],w[7]);
    }
    #pragma unroll
    for (int i = 0; i < 8; i++){
        float dp = 0.f;
        #pragma unroll
        for (int j = 0; j < 8; j++) dp += accA[i][j];
        #pragma unroll
        for (int o = 8; o > 0; o >>= 1) dp += __shfl_xor_sync(0xffffffffu, dp, o);
        if (si == 0) den_s[ti*8 + i] = dp + accD[i];
    }
    __syncthreads();

    // ---- AV: accB += A V ----
    #pragma unroll 4
    for (int s = 0; s < CH2; s++){
        float4 a0 = *(const float4*)&A_T[s*ATS + ti*8];
        float4 a1 = *(const float4*)&A_T[s*ATS + ti*8 + 4];
        float4 vf = *(const float4*)&v_s[s*VS + si*4];
        float av[8] = {a0.x,a0.y,a0.z,a0.w,a1.x,a1.y,a1.z,a1.w};
        float vv[4] = {vf.x,vf.y,vf.z,vf.w};
        #pragma unroll
        for (int i = 0; i < 8; i++)
            #pragma unroll
            for (int j = 0; j < 4; j++) accB[i][j] += av[i]*vv[j];
    }

    // ---- normalize and write ----
    const size_t obase = (((size_t)b*Lc + lbase)*Hc + h)*Dc;
    #pragma unroll
    for (int i = 0; i < 8; i++){
        int t = ti*8 + i;
        float den = den_s[t];
        if (fabsf(den) <= 1e-6f) den += 2e-6f;
        float inv = 1.0f / den;
        float4 o4 = make_float4(accB[i][0]*inv, accB[i][1]*inv,
                                accB[i][2]*inv, accB[i][3]*inv);
        *(float4*)&Out[obase + (size_t)t*(Hc*Dc) + si*4] = o4;
    }
}

// ============================================================
extern "C" void kernel_launch(void* const* d_in, const int* in_sizes, int n_in,
                              void* d_out, int out_size)
{
    const float* Q = (const float*)d_in[0];
    const float* K = (const float*)d_in[1];
    const float* V = (const float*)d_in[2];
    const float* P = (const float*)d_in[3];
    float* O = (float*)d_out;

    const int SM1 = (64*PT_S + 64*XT_S + 64) * 4;                         // ~84 KB
    const int SM3 = (CH2*Mc + CH2*VS) * 4;                                // ~166 KB
    const int SM5 = (32*QTS*2 + 32*VS + 32 + 128*ATS + 128*VS + 128) * 4; // ~146 KB

    cudaFuncSetAttribute(feat_kernel,  cudaFuncAttributeMaxDynamicSharedMemorySize, SM1);
    cudaFuncSetAttribute(state_kernel, cudaFuncAttributeMaxDynamicSharedMemorySize, SM3);
    cudaFuncSetAttribute(out_kernel,   cudaFuncAttributeMaxDynamicSharedMemorySize, SM5);

    init_kernel<<<1, 32>>>();
    feat_kernel<<<NROWS/64, 256, SM1>>>(Q, P, 1);
    feat_kernel<<<NROWS/64, 256, SM1>>>(K, P, 0);
    state_kernel<<<BH*NC2, 256, SM3>>>(V);
    prefix_kernel<<<BH*8, 256>>>();
    out_kernel<<<BH*NC2, 256, SM5>>>(V, O);
}